// round 13
// baseline (speedup 1.0000x reference)
#include <cuda_runtime.h>
#include <cuda_bf16.h>
#include <cstdint>

#define Wd 960
#define Hd 544
#define Td 64
#define PAD 100
#define KSZ 201

#define CH 17              // k16 chunks, K = 272
#define PA 280             // smem pitches (elements); 560B rows -> conflict-free ldsm
#define PB 280
#define P1_N 64
#define P2_N 68            // B padded to 72 rows
#define SMB (64 * PA * 2)  // A region: 64 rows (both passes)
#define P1_SMEM (SMB + 64 * PB * 2)   // 71680
#define P2_SMEM (SMB + 72 * PB * 2)   // 76160
#define TP 68              // transpose buffer pitch
#define NT 512

__device__ __nv_bfloat16 g_mid[(size_t)Td * Wd * Hd];   // [t][c][h]

// ---------------- helpers ----------------------------------------------------
__device__ __forceinline__ uint32_t smem_u32(const void* p) {
    uint32_t a;
    asm("{ .reg .u64 t; cvta.to.shared.u64 t, %1; cvt.u32.u64 %0, t; }"
        : "=r"(a) : "l"(p));
    return a;
}
__device__ __forceinline__ void ldsm4(uint32_t& r0, uint32_t& r1, uint32_t& r2,
                                      uint32_t& r3, uint32_t a) {
    asm volatile("ldmatrix.sync.aligned.m8n8.x4.shared.b16 {%0,%1,%2,%3}, [%4];"
        : "=r"(r0), "=r"(r1), "=r"(r2), "=r"(r3) : "r"(a));
}
__device__ __forceinline__ void ldsm2(uint32_t& r0, uint32_t& r1, uint32_t a) {
    asm volatile("ldmatrix.sync.aligned.m8n8.x2.shared.b16 {%0,%1}, [%2];"
        : "=r"(r0), "=r"(r1) : "r"(a));
}
__device__ __forceinline__ void mma16816(float* d, uint32_t a0, uint32_t a1,
                                         uint32_t a2, uint32_t a3,
                                         uint32_t b0, uint32_t b1) {
    asm volatile("mma.sync.aligned.m16n8k16.row.col.f32.bf16.bf16.f32 "
        "{%0,%1,%2,%3}, {%4,%5,%6,%7}, {%8,%9}, {%0,%1,%2,%3};"
        : "+f"(d[0]), "+f"(d[1]), "+f"(d[2]), "+f"(d[3])
        : "r"(a0), "r"(a1), "r"(a2), "r"(a3), "r"(b0), "r"(b1));
}
// Gaussian weight, computed in-kernel (accuracy ~1e-7 rel; bf16 dominates)
__device__ __forceinline__ float gaussw(int t) {
    float r = (float)(t - PAD);
    return (t >= 0 && t < KSZ) ? __expf(r * r * (-8.0e-4f)) * 0.015957691f : 0.0f;
}

// ---------------- banded mainloop (band-skip, fully unrolled) ---------------
// Block p (8 out-cols at n=8p) uses chunks q with p in [2q-25, 2q+1].
template<int B0, int NB>
__device__ __forceinline__ void band_loop(uint32_t aBase, uint32_t bBase,
                                          uint32_t bPairLane, uint32_t bTailLane,
                                          float (*acc)[4]) {
    const uint32_t bPair = bBase + B0 * 8 * PB * 2 + bPairLane;
    const uint32_t bTail = bBase + (B0 + 2) * 8 * PB * 2 + bTailLane;
#pragma unroll
    for (int q = 0; q < CH; q++) {
        int lo = 2 * q - 25; if (lo < B0) lo = B0;
        int hi = 2 * q + 1;  if (hi > B0 + NB - 1) hi = B0 + NB - 1;
        if (lo > hi) continue;
        uint32_t a0, a1, a2, a3;
        ldsm4(a0, a1, a2, a3, aBase + q * 32);
        bool n0 = (B0 >= lo) && (B0 <= hi);
        bool n1 = (B0 + 1 >= lo) && (B0 + 1 <= hi);
        if (n0 || n1) {
            uint32_t b0, b1, b2, b3;
            ldsm4(b0, b1, b2, b3, bPair + q * 32);
            if (n0) mma16816(acc[0], a0, a1, a2, a3, b0, b1);
            if (n1) mma16816(acc[1], a0, a1, a2, a3, b2, b3);
        }
        if (NB == 3 && (B0 + 2 >= lo) && (B0 + 2 <= hi)) {
            uint32_t b0, b1;
            ldsm2(b0, b1, bTail + q * 32);
            mma16816(acc[2], a0, a1, a2, a3, b0, b1);
        }
    }
}

// ====================== Pass 1: blur along W, write [t][c][h] bf16 ===========
__global__ void __launch_bounds__(NT, 3) p1(const float* __restrict__ x) {
    extern __shared__ char smc[];
    uint32_t sb = smem_u32(smc);
    const int tid = threadIdx.x;
    const int wid = tid >> 5, lid = tid & 31;
    const int wm = wid & 3, h = wid >> 2;     // m-strip (4), n-group (4)
    const int c0 = blockIdx.x * P1_N;
    const int row0 = blockIdx.y * 64;         // flat (t*Hd + h)

    // ---- stage A: 64 rows x 272 k, fp32 -> bf16 ----
    const int gc0 = c0 - PAD;                 // multiple of 4
    for (int i = tid; i < 64 * 34; i += NT) {
        int r = i / 34, j = i % 34;
        int gc = gc0 + j * 8;
        const float* src = x + (size_t)(row0 + r) * Wd + gc;
        float4 a = {0.f, 0.f, 0.f, 0.f}, b = {0.f, 0.f, 0.f, 0.f};
        if (gc >= 0 && gc + 3 < Wd)     a = *(const float4*)(src);
        if (gc + 4 >= 0 && gc + 7 < Wd) b = *(const float4*)(src + 4);
        __nv_bfloat162 q0 = __floats2bfloat162_rn(a.x, a.y);
        __nv_bfloat162 q1 = __floats2bfloat162_rn(a.z, a.w);
        __nv_bfloat162 q2 = __floats2bfloat162_rn(b.x, b.y);
        __nv_bfloat162 q3 = __floats2bfloat162_rn(b.z, b.w);
        uint4 w = { *(uint32_t*)&q0, *(uint32_t*)&q1, *(uint32_t*)&q2, *(uint32_t*)&q3 };
        *(uint4*)(smc + ((size_t)r * PA + j * 8) * 2) = w;
    }
    // ---- stage B: compute band inline ----
    for (int i = tid; i < 64 * 136; i += NT) {
        int n = i / 136, k0 = (i % 136) * 2;
        __nv_bfloat162 wp = __floats2bfloat162_rn(gaussw(k0 - n), gaussw(k0 + 1 - n));
        *(__nv_bfloat162*)(smc + SMB + ((size_t)n * PB + k0) * 2) = wp;
    }
    __syncthreads();

    // ---- mma mainloop ----
    const int mi = lid >> 3, lrow = lid & 7;
    const uint32_t aBase = sb +
        (((wm * 16) + ((mi & 1) << 3) + lrow) * PA + ((mi >> 1) << 3)) * 2;
    const uint32_t bBase = sb + SMB;
    const uint32_t bPairLane = ((((mi >> 1) << 3) + lrow) * PB + (mi & 1) * 8) * 2;
    const uint32_t bTailLane = (((lid & 7)) * PB + ((lid >> 3) & 1) * 8) * 2;

    float acc[2][4];
#pragma unroll
    for (int nb = 0; nb < 2; nb++)
#pragma unroll
        for (int k = 0; k < 4; k++) acc[nb][k] = 0.f;

    if      (h == 0) band_loop<0, 2>(aBase, bBase, bPairLane, bTailLane, acc);
    else if (h == 1) band_loop<2, 2>(aBase, bBase, bPairLane, bTailLane, acc);
    else if (h == 2) band_loop<4, 2>(aBase, bBase, bPairLane, bTailLane, acc);
    else             band_loop<6, 2>(aBase, bBase, bPairLane, bTailLane, acc);
    __syncthreads();   // ldmatrix reads done; smem reusable

    // ---- epilogue: acc -> bf16 transpose buffer tr[c][m] ----
    {
        const int g = lid >> 2, i2 = (lid & 3) * 2;
        const int mrow = wm * 16 + g;
        __nv_bfloat16* tr = (__nv_bfloat16*)smc;
#pragma unroll
        for (int nb = 0; nb < 2; nb++) {
            int c = (2 * h + nb) * 8 + i2;
            tr[c * TP + mrow]           = __float2bfloat16(acc[nb][0]);
            tr[(c + 1) * TP + mrow]     = __float2bfloat16(acc[nb][1]);
            tr[c * TP + mrow + 8]       = __float2bfloat16(acc[nb][2]);
            tr[(c + 1) * TP + mrow + 8] = __float2bfloat16(acc[nb][3]);
        }
    }
    __syncthreads();

    // ---- coalesced store to g_mid[t][c][h] ----
    const int t0 = row0 / Hd, h0 = row0 % Hd;    // h0 multiple of 32
    const int rem = Hd - h0;
    const int len1 = (64 < rem) ? 64 : rem;      // multiple of 32
    const __nv_bfloat16* tr = (const __nv_bfloat16*)smc;
    for (int idx = tid; idx < 64 * 16; idx += NT) {
        int c = idx >> 4, m = (idx & 15) * 4;
        uint2 w = *(const uint2*)(tr + c * TP + m);
        int t = t0, hh = h0 + m;
        if (m >= len1) { t = t0 + 1; hh = m - len1; }
        *(uint2*)(&g_mid[((size_t)t * Wd + (c0 + c)) * Hd + hh]) = w;
    }
}

// ====================== Pass 2: blur along H, write out ======================
__global__ void __launch_bounds__(NT, 3) p2(float* __restrict__ out) {
    extern __shared__ char smc[];
    uint32_t sb = smem_u32(smc);
    const int tid = threadIdx.x;
    const int wid = tid >> 5, lid = tid & 31;
    const int wm = wid & 3, h = wid >> 2;
    const int h0o = blockIdx.x * P2_N;
    const int row0 = blockIdx.y * 64;            // flat (t*Wd + c)

    // ---- stage A: 64 rows x 272 k (bf16 copy from g_mid) ----
    const int gh0 = h0o - PAD;                   // multiple of 4
    for (int i = tid; i < 64 * 34; i += NT) {
        int r = i / 34, j = i % 34;
        int gh = gh0 + j * 8;
        const __nv_bfloat16* src = g_mid + (size_t)(row0 + r) * Hd + gh;
        uint2 w0 = {0u, 0u}, w1 = {0u, 0u};
        if (gh >= 0 && gh + 3 < Hd)     w0 = *(const uint2*)(src);
        if (gh + 4 >= 0 && gh + 7 < Hd) w1 = *(const uint2*)(src + 4);
        uint4 w = {w0.x, w0.y, w1.x, w1.y};
        *(uint4*)(smc + ((size_t)r * PA + j * 8) * 2) = w;
    }
    // ---- stage B: compute band inline (72 rows; n>=68 cols are discarded) ----
    for (int i = tid; i < 72 * 136; i += NT) {
        int n = i / 136, k0 = (i % 136) * 2;
        __nv_bfloat162 wp = __floats2bfloat162_rn(gaussw(k0 - n), gaussw(k0 + 1 - n));
        *(__nv_bfloat162*)(smc + SMB + ((size_t)n * PB + k0) * 2) = wp;
    }
    __syncthreads();

    // ---- mma mainloop ----
    const int mi = lid >> 3, lrow = lid & 7;
    const uint32_t aBase = sb +
        (((wm * 16) + ((mi & 1) << 3) + lrow) * PA + ((mi >> 1) << 3)) * 2;
    const uint32_t bBase = sb + SMB;
    const uint32_t bPairLane = ((((mi >> 1) << 3) + lrow) * PB + (mi & 1) * 8) * 2;
    const uint32_t bTailLane = (((lid & 7)) * PB + ((lid >> 3) & 1) * 8) * 2;

    float acc[3][4];
#pragma unroll
    for (int nb = 0; nb < 3; nb++)
#pragma unroll
        for (int k = 0; k < 4; k++) acc[nb][k] = 0.f;

    if      (h == 0) band_loop<0, 2>(aBase, bBase, bPairLane, bTailLane, acc);
    else if (h == 1) band_loop<2, 2>(aBase, bBase, bPairLane, bTailLane, acc);
    else if (h == 2) band_loop<4, 2>(aBase, bBase, bPairLane, bTailLane, acc);
    else             band_loop<6, 3>(aBase, bBase, bPairLane, bTailLane, acc);
    __syncthreads();

    // ---- epilogue: acc -> f32 transpose buffer tr[n][m] ----
    {
        const int g = lid >> 2, i2 = (lid & 3) * 2;
        const int mrow = wm * 16 + g;
        const int nbs = (h == 3) ? 3 : 2;
        float* tr = (float*)smc;
        for (int nb = 0; nb < nbs; nb++) {
            int c = (2 * h + nb) * 8 + i2;
            tr[c * TP + mrow]           = acc[nb][0];
            tr[(c + 1) * TP + mrow]     = acc[nb][1];
            tr[c * TP + mrow + 8]       = acc[nb][2];
            tr[(c + 1) * TP + mrow + 8] = acc[nb][3];
        }
    }
    __syncthreads();

    // ---- coalesced store to out[t][h][w] (no tile straddle: 960 % 64 == 0) --
    const int t0 = row0 / Wd, cst = row0 % Wd;
    const float* tr = (const float*)smc;
    for (int idx = tid; idx < P2_N * 16; idx += NT) {
        int n = idx >> 4, m = (idx & 15) * 4;
        float4 w = *(const float4*)(tr + n * TP + m);
        *(float4*)(&out[((size_t)t0 * Hd + (h0o + n)) * Wd + cst + m]) = w;
    }
}

// ====================== launch ==============================================
extern "C" void kernel_launch(void* const* d_in, const int* in_sizes, int n_in,
                              void* d_out, int out_size) {
    const float* x = (const float*)d_in[0];
    float* out = (float*)d_out;

    cudaFuncSetAttribute(p1, cudaFuncAttributeMaxDynamicSharedMemorySize, P1_SMEM);
    cudaFuncSetAttribute(p2, cudaFuncAttributeMaxDynamicSharedMemorySize, P2_SMEM);

    p1<<<dim3(Wd / P1_N, (Td * Hd) / 64), NT, P1_SMEM>>>(x);     // 15 x 544
    p2<<<dim3(Hd / P2_N, (Td * Wd) / 64), NT, P2_SMEM>>>(out);   // 8 x 960
}

// round 14
// speedup vs baseline: 1.2584x; 1.2584x over previous
#include <cuda_runtime.h>
#include <cuda_bf16.h>
#include <cstdint>

#define Wd 960
#define Hd 544
#define Td 64
#define PAD 100
#define KSZ 201

#define CH 17               // k16 chunks, K = 272
#define PAe 280             // smem pitch (elements); 560B rows, ldsm conflict-free
#define P1_N 64
#define P2_N 68
#define BKS 272             // g_band row stride (elements)
#define SMB (128 * PAe * 2)             // A region: 128 rows = 71680 B
#define P1_SMEM (SMB + 64 * PAe * 2)    // 107520
#define P2_SMEM (SMB + 72 * PAe * 2)    // 112000
#define TP1 136             // bf16 transpose pitch (m dim)
#define TP2 132             // f32 transpose pitch
#define NT 512

__device__ __nv_bfloat16 g_band[72 * BKS];
__device__ __nv_bfloat16 g_mid[(size_t)Td * Wd * Hd];   // [t][c][h]

// ---------------- constexpr Gaussian weights --------------------------------
__host__ __device__ constexpr double cexp(double x) {
    int n = (int)(x * 1.4426950408889634 - 0.5);   // x <= 0
    double r = x - (double)n * 0.69314718055994530941723212;
    double term = 1.0, p = 1.0;
    for (int k = 1; k <= 16; k++) { term *= r / (double)k; p += term; }
    double s = 1.0;
    for (int i = 0; i < -n; i++) s *= 0.5;
    return p * s;
}
struct GK { float v[KSZ]; };
__host__ __device__ constexpr GK make_gk() {
    GK g{};
    for (int i = 0; i < KSZ; i++) {
        double r = (double)(i - PAD);
        g.v[i] = (float)(cexp(-(r * r) / (2.0 * 25.0 * 25.0)) / 62.665706865775006);
    }
    return g;
}

// ---------------- PTX helpers ------------------------------------------------
__device__ __forceinline__ uint32_t smem_u32(const void* p) {
    uint32_t a;
    asm("{ .reg .u64 t; cvta.to.shared.u64 t, %1; cvt.u32.u64 %0, t; }"
        : "=r"(a) : "l"(p));
    return a;
}
__device__ __forceinline__ void ldsm4(uint32_t& r0, uint32_t& r1, uint32_t& r2,
                                      uint32_t& r3, uint32_t a) {
    asm volatile("ldmatrix.sync.aligned.m8n8.x4.shared.b16 {%0,%1,%2,%3}, [%4];"
        : "=r"(r0), "=r"(r1), "=r"(r2), "=r"(r3) : "r"(a));
}
__device__ __forceinline__ void ldsm2(uint32_t& r0, uint32_t& r1, uint32_t a) {
    asm volatile("ldmatrix.sync.aligned.m8n8.x2.shared.b16 {%0,%1}, [%2];"
        : "=r"(r0), "=r"(r1) : "r"(a));
}
__device__ __forceinline__ void mma16816(float* d, uint32_t a0, uint32_t a1,
                                         uint32_t a2, uint32_t a3,
                                         uint32_t b0, uint32_t b1) {
    asm volatile("mma.sync.aligned.m16n8k16.row.col.f32.bf16.bf16.f32 "
        "{%0,%1,%2,%3}, {%4,%5,%6,%7}, {%8,%9}, {%0,%1,%2,%3};"
        : "+f"(d[0]), "+f"(d[1]), "+f"(d[2]), "+f"(d[3])
        : "r"(a0), "r"(a1), "r"(a2), "r"(a3), "r"(b0), "r"(b1));
}

// ---------------- banded mainloop (band-skip, fully unrolled) ---------------
// Block p (8 out-cols at n=8p) uses chunk q iff p in [2q-25, 2q+1].
// Warp covers blocks B0..B0+2*NP-1 (pairs) plus optional tail block B0+2*NP.
template<int B0, int NP, bool TAIL>
__device__ __forceinline__ void band_loop(uint32_t aBase, uint32_t bPair,
                                          uint32_t bTail, float (*acc)[4]) {
    constexpr int NB = 2 * NP + (TAIL ? 1 : 0);
#pragma unroll
    for (int q = 0; q < CH; q++) {
        int lo = 2 * q - 25; if (lo < B0) lo = B0;
        int hi = 2 * q + 1;  if (hi > B0 + NB - 1) hi = B0 + NB - 1;
        if (lo > hi) continue;
        uint32_t a0, a1, a2, a3;
        ldsm4(a0, a1, a2, a3, aBase + q * 32);
#pragma unroll
        for (int up = 0; up < NP; up++) {
            int u = B0 / 2 + up;
            bool n0 = (2 * u >= lo) && (2 * u <= hi);
            bool n1 = (2 * u + 1 >= lo) && (2 * u + 1 <= hi);
            if (n0 || n1) {
                uint32_t b0, b1, b2, b3;
                ldsm4(b0, b1, b2, b3, bPair + u * (16 * PAe * 2) + q * 32);
                if (n0) mma16816(acc[2 * up],     a0, a1, a2, a3, b0, b1);
                if (n1) mma16816(acc[2 * up + 1], a0, a1, a2, a3, b2, b3);
            }
        }
        if (TAIL && (B0 + 2 * NP >= lo) && (B0 + 2 * NP <= hi)) {
            uint32_t b0, b1;
            ldsm2(b0, b1, bTail + q * 32);
            mma16816(acc[2 * NP], a0, a1, a2, a3, b0, b1);
        }
    }
}

// ---------------- init: band matrix (once, exact table) ---------------------
__global__ void init_bands() {
    constexpr GK gk = make_gk();
    int i = blockIdx.x * 256 + threadIdx.x;
    if (i < 72 * BKS) {
        int n = i / BKS, k = i % BKS;
        int t = k - n;
        float v = (t >= 0 && t < KSZ) ? gk.v[t] : 0.0f;
        g_band[i] = __float2bfloat16(v);
    }
}

// ====================== Pass 1: blur along W, write [t][c][h] bf16 ===========
__global__ void __launch_bounds__(NT, 2) p1(const float* __restrict__ x) {
    extern __shared__ char smc[];
    uint32_t sb = smem_u32(smc);
    const int tid = threadIdx.x;
    const int wid = tid >> 5, lid = tid & 31;
    const int wm = wid & 7, h = wid >> 3;    // 8 m-strips x 2 n-halves
    const int c0 = blockIdx.x * P1_N;
    const int row0 = blockIdx.y * 128;       // flat (t*Hd + h)

    // ---- stage A: 128 rows x 272 k, fp32 -> bf16 ----
    const int gc0 = c0 - PAD;                // multiple of 4
    for (int i = tid; i < 128 * 34; i += NT) {
        int r = i / 34, j = i % 34;
        int gc = gc0 + j * 8;
        const float* src = x + (size_t)(row0 + r) * Wd + gc;
        float4 a = {0.f, 0.f, 0.f, 0.f}, b = {0.f, 0.f, 0.f, 0.f};
        if (gc >= 0 && gc + 3 < Wd)     a = *(const float4*)(src);
        if (gc + 4 >= 0 && gc + 7 < Wd) b = *(const float4*)(src + 4);
        __nv_bfloat162 q0 = __floats2bfloat162_rn(a.x, a.y);
        __nv_bfloat162 q1 = __floats2bfloat162_rn(a.z, a.w);
        __nv_bfloat162 q2 = __floats2bfloat162_rn(b.x, b.y);
        __nv_bfloat162 q3 = __floats2bfloat162_rn(b.z, b.w);
        uint4 w = { *(uint32_t*)&q0, *(uint32_t*)&q1, *(uint32_t*)&q2, *(uint32_t*)&q3 };
        *(uint4*)(smc + ((size_t)r * PAe + j * 8) * 2) = w;
    }
    // ---- stage B: 64 band rows, bulk copy ----
    for (int i = tid; i < 64 * 34; i += NT) {
        int r = i / 34, j = i % 34;
        uint4 w = *(const uint4*)(g_band + r * BKS + j * 8);
        *(uint4*)(smc + SMB + ((size_t)r * PAe + j * 8) * 2) = w;
    }
    __syncthreads();

    // ---- mma mainloop ----
    const int mi = lid >> 3, lrow = lid & 7;
    const uint32_t aBase = sb +
        (((wm * 16) + ((mi & 1) << 3) + lrow) * PAe + ((mi >> 1) << 3)) * 2;
    const uint32_t bPair = sb + SMB +
        ((((mi >> 1) << 3) + lrow) * PAe + (mi & 1) * 8) * 2;

    float acc[4][4];
#pragma unroll
    for (int nb = 0; nb < 4; nb++)
#pragma unroll
        for (int k = 0; k < 4; k++) acc[nb][k] = 0.f;

    if (h == 0) band_loop<0, 2, false>(aBase, bPair, 0u, acc);
    else        band_loop<4, 2, false>(aBase, bPair, 0u, acc);
    __syncthreads();   // ldmatrix reads done; smem reusable

    // ---- epilogue: acc -> bf16 transpose buffer tr[c][m] ----
    {
        const int g = lid >> 2, i2 = (lid & 3) * 2;
        const int mrow = wm * 16 + g;
        __nv_bfloat16* tr = (__nv_bfloat16*)smc;
#pragma unroll
        for (int nb = 0; nb < 4; nb++) {
            int c = (4 * h + nb) * 8 + i2;
            tr[c * TP1 + mrow]           = __float2bfloat16(acc[nb][0]);
            tr[(c + 1) * TP1 + mrow]     = __float2bfloat16(acc[nb][1]);
            tr[c * TP1 + mrow + 8]       = __float2bfloat16(acc[nb][2]);
            tr[(c + 1) * TP1 + mrow + 8] = __float2bfloat16(acc[nb][3]);
        }
    }
    __syncthreads();

    // ---- coalesced store to g_mid[t][c][h] ----
    const int t0 = row0 / Hd, h0 = row0 % Hd;    // h0 multiple of 32
    const int rem = Hd - h0;
    const int len1 = (128 < rem) ? 128 : rem;    // multiple of 32
    const __nv_bfloat16* tr = (const __nv_bfloat16*)smc;
    for (int idx = tid; idx < 64 * 32; idx += NT) {
        int c = idx >> 5, m = (idx & 31) * 4;
        uint2 w = *(const uint2*)(tr + c * TP1 + m);
        int t = t0, hh = h0 + m;
        if (m >= len1) { t = t0 + 1; hh = m - len1; }
        *(uint2*)(&g_mid[((size_t)t * Wd + (c0 + c)) * Hd + hh]) = w;
    }
}

// ====================== Pass 2: blur along H, write out ======================
__global__ void __launch_bounds__(NT, 2) p2(float* __restrict__ out) {
    extern __shared__ char smc[];
    uint32_t sb = smem_u32(smc);
    const int tid = threadIdx.x;
    const int wid = tid >> 5, lid = tid & 31;
    const int wm = wid & 7, h = wid >> 3;
    const int h0o = blockIdx.x * P2_N;
    const int row0 = blockIdx.y * 128;           // flat (t*Wd + c)

    // ---- stage A: 128 rows x 272 k (bf16 copy from g_mid) ----
    const int gh0 = h0o - PAD;                   // multiple of 4
    for (int i = tid; i < 128 * 34; i += NT) {
        int r = i / 34, j = i % 34;
        int gh = gh0 + j * 8;
        const __nv_bfloat16* src = g_mid + (size_t)(row0 + r) * Hd + gh;
        uint2 w0 = {0u, 0u}, w1 = {0u, 0u};
        if (gh >= 0 && gh + 3 < Hd)     w0 = *(const uint2*)(src);
        if (gh + 4 >= 0 && gh + 7 < Hd) w1 = *(const uint2*)(src + 4);
        uint4 w = {w0.x, w0.y, w1.x, w1.y};
        *(uint4*)(smc + ((size_t)r * PAe + j * 8) * 2) = w;
    }
    // ---- stage B: 72 band rows (rows 68-71 feed discarded outputs) ----
    for (int i = tid; i < 72 * 34; i += NT) {
        int r = i / 34, j = i % 34;
        uint4 w = *(const uint4*)(g_band + r * BKS + j * 8);
        *(uint4*)(smc + SMB + ((size_t)r * PAe + j * 8) * 2) = w;
    }
    __syncthreads();

    // ---- mma mainloop ----
    const int mi = lid >> 3, lrow = lid & 7;
    const uint32_t aBase = sb +
        (((wm * 16) + ((mi & 1) << 3) + lrow) * PAe + ((mi >> 1) << 3)) * 2;
    const uint32_t bPair = sb + SMB +
        ((((mi >> 1) << 3) + lrow) * PAe + (mi & 1) * 8) * 2;
    const uint32_t bTail = sb + SMB +
        ((64 + (lid & 7)) * PAe + ((lid >> 3) & 1) * 8) * 2;

    float acc[5][4];
#pragma unroll
    for (int nb = 0; nb < 5; nb++)
#pragma unroll
        for (int k = 0; k < 4; k++) acc[nb][k] = 0.f;

    if (h == 0) band_loop<0, 2, false>(aBase, bPair, bTail, acc);
    else        band_loop<4, 2, true>(aBase, bPair, bTail, acc);
    __syncthreads();

    // ---- epilogue: acc -> f32 transpose buffer tr[n][m] (72 rows alloc) ----
    {
        const int g = lid >> 2, i2 = (lid & 3) * 2;
        const int mrow = wm * 16 + g;
        const int nbs = (h == 0) ? 4 : 5;
        float* tr = (float*)smc;
        for (int nb = 0; nb < nbs; nb++) {
            int c = (4 * h + nb) * 8 + i2;
            tr[c * TP2 + mrow]           = acc[nb][0];
            tr[(c + 1) * TP2 + mrow]     = acc[nb][1];
            tr[c * TP2 + mrow + 8]       = acc[nb][2];
            tr[(c + 1) * TP2 + mrow + 8] = acc[nb][3];
        }
    }
    __syncthreads();

    // ---- coalesced store to out[t][h][w] ----
    const int t0 = row0 / Wd, cst = row0 % Wd;   // cst multiple of 64
    const int rem = Wd - cst;
    const int len1 = (128 < rem) ? 128 : rem;    // multiple of 64
    const float* tr = (const float*)smc;
    for (int idx = tid; idx < P2_N * 32; idx += NT) {
        int n = idx >> 5, m = (idx & 31) * 4;
        float4 w = *(const float4*)(tr + n * TP2 + m);
        int t = t0, c = cst + m;
        if (m >= len1) { t = t0 + 1; c = m - len1; }
        *(float4*)(&out[((size_t)t * Hd + (h0o + n)) * Wd + c]) = w;
    }
}

// ====================== launch ==============================================
extern "C" void kernel_launch(void* const* d_in, const int* in_sizes, int n_in,
                              void* d_out, int out_size) {
    const float* x = (const float*)d_in[0];
    float* out = (float*)d_out;

    cudaFuncSetAttribute(p1, cudaFuncAttributeMaxDynamicSharedMemorySize, P1_SMEM);
    cudaFuncSetAttribute(p2, cudaFuncAttributeMaxDynamicSharedMemorySize, P2_SMEM);

    init_bands<<<(72 * BKS + 255) / 256, 256>>>();
    p1<<<dim3(Wd / P1_N, (Td * Hd) / 128), NT, P1_SMEM>>>(x);    // 15 x 272
    p2<<<dim3(Hd / P2_N, (Td * Wd) / 128), NT, P2_SMEM>>>(out);  // 8 x 480
}

// round 16
// speedup vs baseline: 2.0419x; 1.6227x over previous
#include <cuda_runtime.h>
#include <cuda_bf16.h>
#include <cstdint>

#define Wd 960
#define Hd 544
#define Td 64
#define PAD 100
#define KSZ 201

#define CH 17                    // window chunks (k16 each)
#define PAe 280                  // window pitch (elements); 560B rows conflict-free
#define WINB (128 * PAe * 2)     // 71680
#define SMB  WINB                // B tiles offset
#define BTB  (14 * 16 * 24 * 2)  // 10752 (14 tiles, 16 rows x 48B)
#define TRO  (SMB + BTB)         // 82432
#define TP1 132                  // p1 transpose pitch (bf16), 264B rows (8B-aligned ok)
#define TP2 130                  // p2 transpose pitch (f32), 520B rows (8B-aligned only!)
#define P1_SMEM (TRO + 64 * TP1 * 2)   // 99328
#define P2_SMEM (TRO + 64 * TP2 * 4)   // 115712  (occ-2 ceiling incl. 1KB/CTA reserve)
#define NT 512

__device__ __align__(16) __nv_bfloat16 g_btile[14 * 16 * 24];
__device__ __nv_bfloat16 g_mid[(size_t)Td * Wd * Hd];   // [t][c][h]

// ---------------- constexpr Gaussian weights --------------------------------
__host__ __device__ constexpr double cexp(double x) {
    int n = (int)(x * 1.4426950408889634 - 0.5);   // x <= 0
    double r = x - (double)n * 0.69314718055994530941723212;
    double term = 1.0, p = 1.0;
    for (int k = 1; k <= 16; k++) { term *= r / (double)k; p += term; }
    double s = 1.0;
    for (int i = 0; i < -n; i++) s *= 0.5;
    return p * s;
}
struct GK { float v[KSZ]; };
__host__ __device__ constexpr GK make_gk() {
    GK g{};
    for (int i = 0; i < KSZ; i++) {
        double r = (double)(i - PAD);
        g.v[i] = (float)(cexp(-(r * r) / (2.0 * 25.0 * 25.0)) / 62.665706865775006);
    }
    return g;
}

// ---------------- PTX helpers ------------------------------------------------
__device__ __forceinline__ uint32_t smem_u32(const void* p) {
    uint32_t a;
    asm("{ .reg .u64 t; cvta.to.shared.u64 t, %1; cvt.u32.u64 %0, t; }"
        : "=r"(a) : "l"(p));
    return a;
}
__device__ __forceinline__ void ldsm4(uint32_t& r0, uint32_t& r1, uint32_t& r2,
                                      uint32_t& r3, uint32_t a) {
    asm volatile("ldmatrix.sync.aligned.m8n8.x4.shared.b16 {%0,%1,%2,%3}, [%4];"
        : "=r"(r0), "=r"(r1), "=r"(r2), "=r"(r3) : "r"(a));
}
__device__ __forceinline__ void mma16816(float* d, uint32_t a0, uint32_t a1,
                                         uint32_t a2, uint32_t a3,
                                         uint32_t b0, uint32_t b1) {
    asm volatile("mma.sync.aligned.m16n8k16.row.col.f32.bf16.bf16.f32 "
        "{%0,%1,%2,%3}, {%4,%5,%6,%7}, {%8,%9}, {%0,%1,%2,%3};"
        : "+f"(d[0]), "+f"(d[1]), "+f"(d[2]), "+f"(d[3])
        : "r"(a0), "r"(a1), "r"(a2), "r"(a3), "r"(b0), "r"(b1));
}

// ---------------- staging helpers (8 cols, 4-col guard granularity) ---------
__device__ __forceinline__ void stage8f(const float* src, int gc, void* dst) {
    float4 a = {0.f, 0.f, 0.f, 0.f}, b = {0.f, 0.f, 0.f, 0.f};
    if (gc >= 0 && gc + 3 < Wd)     a = *(const float4*)(src);
    if (gc + 4 >= 0 && gc + 7 < Wd) b = *(const float4*)(src + 4);
    __nv_bfloat162 q0 = __floats2bfloat162_rn(a.x, a.y);
    __nv_bfloat162 q1 = __floats2bfloat162_rn(a.z, a.w);
    __nv_bfloat162 q2 = __floats2bfloat162_rn(b.x, b.y);
    __nv_bfloat162 q3 = __floats2bfloat162_rn(b.z, b.w);
    uint4 w = { *(uint32_t*)&q0, *(uint32_t*)&q1, *(uint32_t*)&q2, *(uint32_t*)&q3 };
    *(uint4*)dst = w;
}
__device__ __forceinline__ void stage8h(const __nv_bfloat16* src, int gh, void* dst) {
    uint2 w0 = {0u, 0u}, w1 = {0u, 0u};
    if (gh >= 0 && gh + 3 < Hd)     w0 = *(const uint2*)(src);
    if (gh + 4 >= 0 && gh + 7 < Hd) w1 = *(const uint2*)(src + 4);
    uint4 w = {w0.x, w0.y, w1.x, w1.y};
    *(uint4*)dst = w;
}

// ---------------- per-step MMA: relative-B band loop ------------------------
// Chunk i in window (abs q = 4s+i). Warp half HH covers n-pairs P=2HH (acc0/1)
// and P=2HH+1 (acc2/3); tile index e = i - P, valid iff e in [0,13].
template<int HH>
__device__ __forceinline__ void step_mma(uint32_t aBase, uint32_t bBase,
                                         int s4, float acc[4][4]) {
#pragma unroll
    for (int i = 0; i < CH; i++) {
        const int  e0 = i - 2 * HH;
        const int  e1 = e0 - 1;
        const bool v0 = (e0 >= 0) && (e0 <= 13);
        const bool v1 = (e1 >= 0) && (e1 <= 13);
        if (!(v0 || v1)) continue;
        int slot = s4 + i; if (slot >= CH) slot -= CH;
        uint32_t a0, a1, a2, a3;
        ldsm4(a0, a1, a2, a3, aBase + slot * 32);
        if (v0) {
            uint32_t b0, b1, b2, b3;
            ldsm4(b0, b1, b2, b3, bBase + e0 * 768);
            mma16816(acc[0], a0, a1, a2, a3, b0, b1);
            mma16816(acc[1], a0, a1, a2, a3, b2, b3);
        }
        if (v1) {
            uint32_t b0, b1, b2, b3;
            ldsm4(b0, b1, b2, b3, bBase + e1 * 768);
            mma16816(acc[2], a0, a1, a2, a3, b0, b1);
            mma16816(acc[3], a0, a1, a2, a3, b2, b3);
        }
    }
}

// ---------------- init: 14 relative 16x16 B tiles, 48B-padded rows ----------
__global__ void init_bt() {
    constexpr GK gk = make_gk();
    int i = blockIdx.x * 256 + threadIdx.x;
    if (i < 14 * 16 * 24) {
        int e = i / (16 * 24);
        int r = (i / 24) % 16;
        int k = i % 24;
        int t = 16 * e + k - r;
        float v = (k < 16 && t >= 0 && t < KSZ) ? gk.v[t] : 0.0f;
        g_btile[i] = __float2bfloat16(v);
    }
}

// ====================== Pass 1: persistent row-strip, blur along W ==========
__global__ void __launch_bounds__(NT, 2) p1(const float* __restrict__ x) {
    extern __shared__ char smc[];
    uint32_t sb = smem_u32(smc);
    const int tid = threadIdx.x;
    const int wid = tid >> 5, lid = tid & 31;
    const int wm = wid & 7, hh = wid >> 3;
    const int row0 = blockIdx.x * 128;           // flat (t*Hd + h)

    // stage B tiles once
    for (int i = tid; i < BTB / 16; i += NT)
        ((uint4*)(smc + SMB))[i] = ((const uint4*)g_btile)[i];
    // initial window: chunks 0..16 = input cols [-100, 172)
    for (int i = tid; i < 128 * 34; i += NT) {
        int r = i / 34, j = i % 34;
        int gc = j * 8 - PAD;
        stage8f(x + (size_t)(row0 + r) * Wd + gc, gc,
                smc + ((size_t)r * PAe + j * 8) * 2);
    }
    __syncthreads();

    const int mi = lid >> 3, lrow = lid & 7;
    const uint32_t aBase = sb +
        (((wm * 16) + ((mi & 1) << 3) + lrow) * PAe + ((mi >> 1) << 3)) * 2;
    const uint32_t bBase = sb + SMB + ((((mi >> 1) << 3) + lrow) * 48 + (mi & 1) * 16);

    const int t0g = row0 / Hd, h0g = row0 % Hd;  // h0g multiple of 32
    const int rem = Hd - h0g;
    const int len1 = (128 < rem) ? 128 : rem;

    int s4 = 0;
    for (int s = 0; s < 15; s++) {
        float acc[4][4];
#pragma unroll
        for (int nb = 0; nb < 4; nb++)
#pragma unroll
            for (int k = 0; k < 4; k++) acc[nb][k] = 0.f;

        if (hh == 0) step_mma<0>(aBase, bBase, s4, acc);
        else         step_mma<1>(aBase, bBase, s4, acc);
        __syncthreads();                          // window + prev tr reads done

        // epilogue -> bf16 transpose buffer tr[c][m]
        {
            const int g = lid >> 2, i2 = (lid & 3) * 2;
            const int mrow = wm * 16 + g;
            __nv_bfloat16* tr = (__nv_bfloat16*)(smc + TRO);
#pragma unroll
            for (int nb = 0; nb < 4; nb++) {
                int c = (4 * hh + nb) * 8 + i2;
                tr[c * TP1 + mrow]           = __float2bfloat16(acc[nb][0]);
                tr[(c + 1) * TP1 + mrow]     = __float2bfloat16(acc[nb][1]);
                tr[c * TP1 + mrow + 8]       = __float2bfloat16(acc[nb][2]);
                tr[(c + 1) * TP1 + mrow + 8] = __float2bfloat16(acc[nb][3]);
            }
        }
        // stage next 4 chunks (q = 4s+17 .. 4s+20) into retired slots
        if (s < 14) {
            int cstart = 64 * s + 172;            // 16*(4s+17) - 100
#pragma unroll
            for (int it = 0; it < 2; it++) {
                int id = tid + it * NT;
                int r = id >> 3, hc = id & 7;
                int slot = s4 + (hc >> 1); if (slot >= CH) slot -= CH;
                int gc = cstart + hc * 8;
                stage8f(x + (size_t)(row0 + r) * Wd + gc, gc,
                        smc + ((size_t)r * PAe + slot * 16 + (hc & 1) * 8) * 2);
            }
        }
        __syncthreads();                          // tr + staged visible

        // coalesced store to g_mid[t][c][h]
        const int c0 = s * 64;
        const __nv_bfloat16* tr = (const __nv_bfloat16*)(smc + TRO);
        for (int idx = tid; idx < 64 * 32; idx += NT) {
            int c = idx >> 5, m = (idx & 31) * 4;
            uint2 w = *(const uint2*)(tr + c * TP1 + m);
            int t = t0g, hcol = h0g + m;
            if (m >= len1) { t = t0g + 1; hcol = m - len1; }
            *(uint2*)(&g_mid[((size_t)t * Wd + (c0 + c)) * Hd + hcol]) = w;
        }
        s4 += 4; if (s4 >= CH) s4 -= CH;
    }
}

// ====================== Pass 2: persistent row-strip, blur along H ==========
__global__ void __launch_bounds__(NT, 2) p2(float* __restrict__ out) {
    extern __shared__ char smc[];
    uint32_t sb = smem_u32(smc);
    const int tid = threadIdx.x;
    const int wid = tid >> 5, lid = tid & 31;
    const int wm = wid & 7, hh = wid >> 3;
    const int row0 = blockIdx.x * 128;           // flat (t*Wd + c)

    for (int i = tid; i < BTB / 16; i += NT)
        ((uint4*)(smc + SMB))[i] = ((const uint4*)g_btile)[i];
    for (int i = tid; i < 128 * 34; i += NT) {
        int r = i / 34, j = i % 34;
        int gh = j * 8 - PAD;
        stage8h(g_mid + (size_t)(row0 + r) * Hd + gh, gh,
                smc + ((size_t)r * PAe + j * 8) * 2);
    }
    __syncthreads();

    const int mi = lid >> 3, lrow = lid & 7;
    const uint32_t aBase = sb +
        (((wm * 16) + ((mi & 1) << 3) + lrow) * PAe + ((mi >> 1) << 3)) * 2;
    const uint32_t bBase = sb + SMB + ((((mi >> 1) << 3) + lrow) * 48 + (mi & 1) * 16);

    const int t0g = row0 / Wd, cst = row0 % Wd;  // cst multiple of 64
    const int rem = Wd - cst;
    const int len1 = (128 < rem) ? 128 : rem;    // multiple of 64

    int s4 = 0;
    for (int s = 0; s < 9; s++) {                // 8 full steps + 32-col tail
        const bool full = (s < 8);
        float acc[4][4];
#pragma unroll
        for (int nb = 0; nb < 4; nb++)
#pragma unroll
            for (int k = 0; k < 4; k++) acc[nb][k] = 0.f;

        if (hh == 0)   step_mma<0>(aBase, bBase, s4, acc);
        else if (full) step_mma<1>(aBase, bBase, s4, acc);
        __syncthreads();

        if (hh == 0 || full) {
            const int g = lid >> 2, i2 = (lid & 3) * 2;
            const int mrow = wm * 16 + g;
            float* tr = (float*)(smc + TRO);
#pragma unroll
            for (int nb = 0; nb < 4; nb++) {
                int c = (4 * hh + nb) * 8 + i2;
                tr[c * TP2 + mrow]           = acc[nb][0];
                tr[(c + 1) * TP2 + mrow]     = acc[nb][1];
                tr[c * TP2 + mrow + 8]       = acc[nb][2];
                tr[(c + 1) * TP2 + mrow + 8] = acc[nb][3];
            }
        }
        if (full) {                               // stage q = 4s+17..4s+20, q <= 46
            int cstart = 64 * s + 172;
#pragma unroll
            for (int it = 0; it < 2; it++) {
                int id = tid + it * NT;
                int r = id >> 3, hc = id & 7;
                int q = 4 * s + 17 + (hc >> 1);
                if (q <= 46) {
                    int slot = s4 + (hc >> 1); if (slot >= CH) slot -= CH;
                    int gh = cstart + hc * 8;
                    stage8h(g_mid + (size_t)(row0 + r) * Hd + gh, gh,
                            smc + ((size_t)r * PAe + slot * 16 + (hc & 1) * 8) * 2);
                }
            }
        }
        __syncthreads();

        // store: float2 pairs (TP2=130 -> 520B rows are 8B-aligned, NOT 16B)
        const int h0o = s * 64;
        const int ncols = full ? 64 : 32;
        const float* tr = (const float*)(smc + TRO);
        for (int idx = tid; idx < ncols * 32; idx += NT) {
            int n = idx >> 5, m = (idx & 31) * 4;
            float2 w01 = *(const float2*)(tr + n * TP2 + m);
            float2 w23 = *(const float2*)(tr + n * TP2 + m + 2);
            int t = t0g, c = cst + m;
            if (m >= len1) { t = t0g + 1; c = m - len1; }
            float* dst = &out[((size_t)t * Hd + (h0o + n)) * Wd + c];
            *(float2*)(dst)     = w01;
            *(float2*)(dst + 2) = w23;
        }
        s4 += 4; if (s4 >= CH) s4 -= CH;
    }
}

// ====================== launch ==============================================
extern "C" void kernel_launch(void* const* d_in, const int* in_sizes, int n_in,
                              void* d_out, int out_size) {
    const float* x = (const float*)d_in[0];
    float* out = (float*)d_out;

    cudaFuncSetAttribute(p1, cudaFuncAttributeMaxDynamicSharedMemorySize, P1_SMEM);
    cudaFuncSetAttribute(p2, cudaFuncAttributeMaxDynamicSharedMemorySize, P2_SMEM);

    init_bt<<<(14 * 16 * 24 + 255) / 256, 256>>>();
    p1<<<(Td * Hd) / 128, NT, P1_SMEM>>>(x);     // 272 CTAs
    p2<<<(Td * Wd) / 128, NT, P2_SMEM>>>(out);   // 480 CTAs
}